// round 7
// baseline (speedup 1.0000x reference)
#include <cuda_runtime.h>
#include <cuda_bf16.h>
#include <math.h>

#define MAXN 100000
#define MAXE 1200000
#define D    64
#define HID  128
#define C    40
#define NB   ((MAXN + 255) / 256)

// ---------------- device scratch ----------------
__device__ int   d_deg[MAXN];
__device__ int   d_cursor[MAXN];
__device__ int   d_rowptr[MAXN + 1];
__device__ int   d_col[MAXE];
__device__ int   d_bsum[NB];
__device__ int   d_boff[NB];
__device__ __align__(16) float d_y[(size_t)MAXN * C];

// packed f32x2 helpers
__device__ __forceinline__ unsigned long long bc2(float x) {      // broadcast pack
    unsigned long long r;
    asm("mov.b64 %0, {%1,%1};" : "=l"(r) : "f"(x));
    return r;
}
#define FMA2(d, a, b, c) asm("fma.rn.f32x2 %0, %1, %2, %3;" : "=l"(d) : "l"(a), "l"(b), "l"(c))
#define ADD2(d, a, b)    asm("add.rn.f32x2 %0, %1, %2;" : "=l"(d) : "l"(a), "l"(b))
__device__ __forceinline__ void upk2(float& x, float& y, unsigned long long v) {
    asm("mov.b64 {%0,%1}, %2;" : "=f"(x), "=f"(y) : "l"(v));
}

// ---------------- CSR build ----------------
__global__ void k_init(int n) {
    int i = blockIdx.x * blockDim.x + threadIdx.x;
    if (i < n) { d_deg[i] = 0; d_cursor[i] = 0; }
}

__global__ void k_count(const int2* __restrict__ adj, int e) {
    int i = blockIdx.x * blockDim.x + threadIdx.x;
    if (i < e) atomicAdd(&d_deg[adj[i].y], 1);
}

__global__ void k_scan1(int n) {
    __shared__ int sh[256];
    int t = threadIdx.x;
    int i = blockIdx.x * 256 + t;
    int v = (i < n) ? d_deg[i] : 0;
    sh[t] = v;
    __syncthreads();
#pragma unroll
    for (int off = 1; off < 256; off <<= 1) {
        int add = (t >= off) ? sh[t - off] : 0;
        __syncthreads();
        sh[t] += add;
        __syncthreads();
    }
    if (i < n) d_rowptr[i] = sh[t] - v;
    if (t == 255) d_bsum[blockIdx.x] = sh[255];
}

__global__ void k_scan2(int nb, int n) {
    __shared__ int sh[512];
    int t = threadIdx.x;
    int v = (t < nb) ? d_bsum[t] : 0;
    sh[t] = v;
    __syncthreads();
#pragma unroll
    for (int off = 1; off < 512; off <<= 1) {
        int add = (t >= off) ? sh[t - off] : 0;
        __syncthreads();
        sh[t] += add;
        __syncthreads();
    }
    if (t < nb) d_boff[t] = sh[t] - v;
    if (t == nb - 1) d_rowptr[n] = sh[t];
}

__global__ void k_scan3(int n) {
    int i = blockIdx.x * 256 + threadIdx.x;
    if (i < n) d_rowptr[i] += d_boff[blockIdx.x];
}

__global__ void k_scatter(const int2* __restrict__ adj, int e) {
    int i = blockIdx.x * blockDim.x + threadIdx.x;
    if (i < e) {
        int2 ed = adj[i];
        int p = atomicAdd(&d_cursor[ed.y], 1);
        d_col[d_rowptr[ed.y] + p] = ed.x;
    }
}

// ---------------- fused: agg1 + GEMM1 + ReLU + GEMM2 -> d_y ----------------
#define SM_W1 0
#define SM_W2 8192
#define SM_AT 13312
#define SM_X  17664
#define SM_TOTAL_F 25984   // 103936 bytes

__global__ void __launch_bounds__(256) k_fused(const float* __restrict__ h,
                                               const float* __restrict__ W1,
                                               const float* __restrict__ b1,
                                               const float* __restrict__ W2,
                                               int n) {
    extern __shared__ float smem[];
    float* sW1 = smem + SM_W1;
    float* sW2 = smem + SM_W2;
    float* sAT = smem + SM_AT;   // [k][node] stride 68 (16B rows)
    float* sX  = smem + SM_X;    // [hid][node] stride 65

    int tid = threadIdx.x;
    int node0 = blockIdx.x * 64;

    {
        const float4* W4 = (const float4*)W1;
        float4* s4 = (float4*)sW1;
#pragma unroll
        for (int i = 0; i < 8; i++) s4[tid + i * 256] = W4[tid + i * 256];
        const float4* V4 = (const float4*)W2;
        float4* t4 = (float4*)sW2;
#pragma unroll
        for (int i = 0; i < 5; i++) t4[tid + i * 256] = V4[tid + i * 256];
    }

    // ---- phase 0: gather-aggregate; half-warp x 16B, f32x2 adds ----
    {
        int w = tid >> 5, lane = tid & 31;
        int half = lane >> 4;
        int q = lane & 15;
        const ulonglong2* h8 = (const ulonglong2*)h;   // 16B granules
#pragma unroll
        for (int ii = 0; ii < 8; ii++) {
            int nodeL = w * 8 + ii;
            int gn = node0 + nodeL;
            unsigned long long aA = 0ull, aB = 0ull;
            if (gn < n) {
                if (half == 0) {
                    ulonglong2 s = h8[(size_t)gn * 16 + q];
                    aA = s.x; aB = s.y;
                }
                int beg = d_rowptr[gn], end = d_rowptr[gn + 1];
                int j = beg;
                for (; j + 3 < end; j += 4) {
                    int s0 = d_col[j + half];
                    int s1 = d_col[j + 2 + half];
                    ulonglong2 v0 = h8[(size_t)s0 * 16 + q];
                    ulonglong2 v1 = h8[(size_t)s1 * 16 + q];
                    ADD2(aA, aA, v0.x); ADD2(aB, aB, v0.y);
                    ADD2(aA, aA, v1.x); ADD2(aB, aB, v1.y);
                }
                if (j + 1 < end) {
                    int s = d_col[j + half];
                    ulonglong2 v = h8[(size_t)s * 16 + q];
                    ADD2(aA, aA, v.x); ADD2(aB, aB, v.y);
                    j += 2;
                }
                if (j < end && half == 0) {
                    int s = d_col[j];
                    ulonglong2 v = h8[(size_t)s * 16 + q];
                    ADD2(aA, aA, v.x); ADD2(aB, aB, v.y);
                }
            }
            float ax, ay, az, aw;
            upk2(ax, ay, aA);
            upk2(az, aw, aB);
            ax += __shfl_xor_sync(0xffffffffu, ax, 16);
            ay += __shfl_xor_sync(0xffffffffu, ay, 16);
            az += __shfl_xor_sync(0xffffffffu, az, 16);
            aw += __shfl_xor_sync(0xffffffffu, aw, 16);
            if (half == 0) {
                sAT[(4 * q + 0) * 68 + nodeL] = ax;
                sAT[(4 * q + 1) * 68 + nodeL] = ay;
                sAT[(4 * q + 2) * 68 + nodeL] = az;
                sAT[(4 * q + 3) * 68 + nodeL] = aw;
            }
        }
    }
    __syncthreads();

    // ---- phase 1: x1 = relu(agg @ W1 + b1), f32x2; weight pairs loaded as b64 ----
    {
        int ng = tid & 15;    // nodes ng*4 .. +3
        int og = tid >> 4;    // hids  og*8 .. +7 (4 pairs)
        unsigned long long acc2[4][4];
#pragma unroll
        for (int i = 0; i < 4; i++)
#pragma unroll
            for (int jp = 0; jp < 4; jp++) acc2[i][jp] = 0ull;

#pragma unroll
        for (int k = 0; k < D; k++) {
            float4 a4 = *(const float4*)&sAT[k * 68 + ng * 4];
            unsigned long long av[4] = {bc2(a4.x), bc2(a4.y), bc2(a4.z), bc2(a4.w)};
            ulonglong2 wA = *(const ulonglong2*)&sW1[k * HID + og * 8];      // pairs 0,1
            ulonglong2 wB = *(const ulonglong2*)&sW1[k * HID + og * 8 + 4];  // pairs 2,3
#pragma unroll
            for (int i = 0; i < 4; i++) {
                FMA2(acc2[i][0], av[i], wA.x, acc2[i][0]);
                FMA2(acc2[i][1], av[i], wA.y, acc2[i][1]);
                FMA2(acc2[i][2], av[i], wB.x, acc2[i][2]);
                FMA2(acc2[i][3], av[i], wB.y, acc2[i][3]);
            }
        }

        float bb[8];
#pragma unroll
        for (int j = 0; j < 8; j++) bb[j] = b1[og * 8 + j];
#pragma unroll
        for (int i = 0; i < 4; i++) {
#pragma unroll
            for (int jp = 0; jp < 4; jp++) {
                float lo, hi_;
                upk2(lo, hi_, acc2[i][jp]);
                sX[(og * 8 + 2 * jp) * 65 + (ng * 4 + i)]     = fmaxf(lo + bb[2 * jp], 0.f);
                sX[(og * 8 + 2 * jp + 1) * 65 + (ng * 4 + i)] = fmaxf(hi_ + bb[2 * jp + 1], 0.f);
            }
        }
    }
    __syncthreads();

    // ---- phase 2: y = x1 @ W2; 1 node x 5 out-pairs per thread ----
    {
        int og = tid & 3;     // outs og*10 .. +9 (5 pairs)
        int ng = tid >> 2;    // node 0..63
        const unsigned long long* w8 = (const unsigned long long*)sW2;  // pair idx = k*20 + og*5 + jj
        unsigned long long acc2[5] = {0ull, 0ull, 0ull, 0ull, 0ull};

#pragma unroll 4
        for (int k = 0; k < HID; k++) {
            unsigned long long av = bc2(sX[k * 65 + ng]);
            int base = k * 20 + og * 5;
#pragma unroll
            for (int jj = 0; jj < 5; jj++)
                FMA2(acc2[jj], av, w8[base + jj], acc2[jj]);
        }
        int gn = node0 + ng;
        if (gn < n) {
            unsigned long long* yo = (unsigned long long*)(d_y + (size_t)gn * C + og * 10);
#pragma unroll
            for (int jj = 0; jj < 5; jj++) yo[jj] = acc2[jj];
        }
    }
}

// ---------------- layer-2 aggregation + bias + softmax ----------------
__global__ void k_agg2_softmax(const float* __restrict__ b2, float* __restrict__ out, int n) {
    int w = (blockIdx.x * blockDim.x + threadIdx.x) >> 5;
    int lane = threadIdx.x & 31;
    if (w >= n) return;

    int g = lane / 10;
    int q = lane - g * 10;
    bool act = (lane < 30);
    const ulonglong2* Y8 = (const ulonglong2*)d_y;

    unsigned long long aA = 0ull, aB = 0ull;
    if (act && g == 0) {
        ulonglong2 s = Y8[(size_t)w * 10 + q];
        aA = s.x; aB = s.y;
    }

    int beg = d_rowptr[w], end = d_rowptr[w + 1];
    int j = beg;
    for (; j + 5 < end; j += 6) {
        if (act) {
            int s0 = d_col[j + g];
            int s1 = d_col[j + 3 + g];
            ulonglong2 v0 = Y8[(size_t)s0 * 10 + q];
            ulonglong2 v1 = Y8[(size_t)s1 * 10 + q];
            ADD2(aA, aA, v0.x); ADD2(aB, aB, v0.y);
            ADD2(aA, aA, v1.x); ADD2(aB, aB, v1.y);
        }
    }
    if (j + 2 < end) {
        if (act) {
            int s = d_col[j + g];
            ulonglong2 v = Y8[(size_t)s * 10 + q];
            ADD2(aA, aA, v.x); ADD2(aB, aB, v.y);
        }
        j += 3;
    }
    int rem = end - j;
    if (act && g < rem) {
        int s = d_col[j + g];
        ulonglong2 v = Y8[(size_t)s * 10 + q];
        ADD2(aA, aA, v.x); ADD2(aB, aB, v.y);
    }

    float ax, ay, az, aw;
    upk2(ax, ay, aA);
    upk2(az, aw, aB);
    ax += __shfl_sync(0xffffffffu, ax, lane + 10) + __shfl_sync(0xffffffffu, ax, lane + 20);
    ay += __shfl_sync(0xffffffffu, ay, lane + 10) + __shfl_sync(0xffffffffu, ay, lane + 20);
    az += __shfl_sync(0xffffffffu, az, lane + 10) + __shfl_sync(0xffffffffu, az, lane + 20);
    aw += __shfl_sync(0xffffffffu, aw, lane + 10) + __shfl_sync(0xffffffffu, aw, lane + 20);

    bool own = (lane < 10);
    if (own) {
        ax += b2[lane * 4 + 0];
        ay += b2[lane * 4 + 1];
        az += b2[lane * 4 + 2];
        aw += b2[lane * 4 + 3];
    }
    float m = own ? fmaxf(fmaxf(ax, ay), fmaxf(az, aw)) : -1e30f;
#pragma unroll
    for (int off = 16; off; off >>= 1)
        m = fmaxf(m, __shfl_xor_sync(0xffffffffu, m, off));
    float e0 = __expf(ax - m);
    float e1 = __expf(ay - m);
    float e2 = __expf(az - m);
    float e3 = __expf(aw - m);
    float s = own ? (e0 + e1) + (e2 + e3) : 0.f;
#pragma unroll
    for (int off = 16; off; off >>= 1)
        s += __shfl_xor_sync(0xffffffffu, s, off);
    float inv = 1.f / s;
    if (own) {
        float* o = out + (size_t)w * C + lane * 4;
        o[0] = e0 * inv;
        o[1] = e1 * inv;
        o[2] = e2 * inv;
        o[3] = e3 * inv;
    }
}

// ---------------- launch ----------------
extern "C" void kernel_launch(void* const* d_in, const int* in_sizes, int n_in,
                              void* d_out, int out_size) {
    const float* h   = (const float*)d_in[0];
    const int*   adj = (const int*)d_in[1];
    const float* W1  = (const float*)d_in[2];
    const float* b1  = (const float*)d_in[3];
    const float* W2  = (const float*)d_in[4];
    const float* b2  = (const float*)d_in[5];
    float* out = (float*)d_out;

    int n = in_sizes[0] / D;
    int e = in_sizes[1] / 2;
    if (n > MAXN) n = MAXN;
    if (e > MAXE) e = MAXE;
    int nb = (n + 255) / 256;

    cudaFuncSetAttribute(k_fused, cudaFuncAttributeMaxDynamicSharedMemorySize,
                         SM_TOTAL_F * (int)sizeof(float));

    k_init<<<(n + 255) / 256, 256>>>(n);
    k_count<<<(e + 255) / 256, 256>>>((const int2*)adj, e);
    k_scan1<<<nb, 256>>>(n);
    k_scan2<<<1, 512>>>(nb, n);
    k_scan3<<<nb, 256>>>(n);
    k_scatter<<<(e + 255) / 256, 256>>>((const int2*)adj, e);

    k_fused<<<(n + 63) / 64, 256, SM_TOTAL_F * sizeof(float)>>>(h, W1, b1, W2, n);
    k_agg2_softmax<<<(n * 32 + 255) / 256, 256>>>(b2, out, n);
}

// round 8
// speedup vs baseline: 1.1059x; 1.1059x over previous
#include <cuda_runtime.h>
#include <cuda_bf16.h>
#include <math.h>

#define MAXN 100000
#define MAXE 1200000
#define D    64
#define HID  128
#define C    40
#define NB   ((MAXN + 255) / 256)

// ---------------- device scratch ----------------
__device__ int   d_deg[MAXN];
__device__ int   d_rowptr[MAXN + 1];
__device__ int   d_col[MAXE];
__device__ int   d_slot[MAXE];
__device__ int   d_bsum[NB];
__device__ int   d_boff[NB];
__device__ __align__(16) float d_y[(size_t)MAXN * C];

// ---------------- CSR build ----------------
__global__ void k_init(int n) {
    int i = blockIdx.x * blockDim.x + threadIdx.x;
    if (i < n) d_deg[i] = 0;
}

// count + record slot (the only atomic pass)
__global__ void k_count(const int2* __restrict__ adj, int e) {
    int i = blockIdx.x * blockDim.x + threadIdx.x;
    if (i < e) {
        int2 ed = adj[i];
        d_slot[i] = atomicAdd(&d_deg[ed.y], 1);
    }
}

__global__ void k_scan1(int n) {
    __shared__ int sh[256];
    int t = threadIdx.x;
    int i = blockIdx.x * 256 + t;
    int v = (i < n) ? d_deg[i] : 0;
    sh[t] = v;
    __syncthreads();
#pragma unroll
    for (int off = 1; off < 256; off <<= 1) {
        int add = (t >= off) ? sh[t - off] : 0;
        __syncthreads();
        sh[t] += add;
        __syncthreads();
    }
    if (i < n) d_rowptr[i] = sh[t] - v;
    if (t == 255) d_bsum[blockIdx.x] = sh[255];
}

__global__ void k_scan2(int nb, int n) {
    __shared__ int sh[512];
    int t = threadIdx.x;
    int v = (t < nb) ? d_bsum[t] : 0;
    sh[t] = v;
    __syncthreads();
#pragma unroll
    for (int off = 1; off < 512; off <<= 1) {
        int add = (t >= off) ? sh[t - off] : 0;
        __syncthreads();
        sh[t] += add;
        __syncthreads();
    }
    if (t < nb) d_boff[t] = sh[t] - v;
    if (t == nb - 1) d_rowptr[n] = sh[t];
}

__global__ void k_scan3(int n) {
    int i = blockIdx.x * 256 + threadIdx.x;
    if (i < n) d_rowptr[i] += d_boff[blockIdx.x];
}

// atomic-free scatter
__global__ void k_scatter(const int2* __restrict__ adj, int e) {
    int i = blockIdx.x * blockDim.x + threadIdx.x;
    if (i < e) {
        int2 ed = adj[i];
        d_col[d_rowptr[ed.y] + d_slot[i]] = ed.x;
    }
}

// ---------------- fused: agg1 + GEMM1 + ReLU + GEMM2 -> d_y ----------------
// smem floats: sW1[64*128]=8192 | sW2[128*40]=5120 | sAT[64][68]=4352 | sX[128][68]=8704
#define SM_W1 0
#define SM_W2 8192
#define SM_AT 13312
#define SM_X  17664
#define SM_TOTAL_F 26368   // 105472 bytes

__global__ void __launch_bounds__(256) k_fused(const float* __restrict__ h,
                                               const float* __restrict__ W1,
                                               const float* __restrict__ b1,
                                               const float* __restrict__ W2,
                                               int n) {
    extern __shared__ float smem[];
    float* sW1 = smem + SM_W1;
    float* sW2 = smem + SM_W2;
    float* sAT = smem + SM_AT;   // [k][node] stride 68 (16B rows)
    float* sX  = smem + SM_X;    // [hid][node] stride 68 (16B rows)

    int tid = threadIdx.x;
    int node0 = blockIdx.x * 64;

    {
        const float4* W4 = (const float4*)W1;
        float4* s4 = (float4*)sW1;
#pragma unroll
        for (int i = 0; i < 8; i++) s4[tid + i * 256] = W4[tid + i * 256];
        const float4* V4 = (const float4*)W2;
        float4* t4 = (float4*)sW2;
#pragma unroll
        for (int i = 0; i < 5; i++) t4[tid + i * 256] = V4[tid + i * 256];
    }

    // ---- phase 0: gather-aggregate; half-warp x float4 ----
    {
        int w = tid >> 5, lane = tid & 31;
        int half = lane >> 4;
        int q = lane & 15;
        const float4* h4 = (const float4*)h;
#pragma unroll
        for (int ii = 0; ii < 8; ii++) {
            int nodeL = w * 8 + ii;
            int gn = node0 + nodeL;
            float4 acc = make_float4(0.f, 0.f, 0.f, 0.f);
            if (gn < n) {
                if (half == 0) acc = h4[(size_t)gn * 16 + q];
                int beg = d_rowptr[gn], end = d_rowptr[gn + 1];
                int j = beg;
                for (; j + 3 < end; j += 4) {
                    int s0 = d_col[j + half];
                    int s1 = d_col[j + 2 + half];
                    float4 v0 = h4[(size_t)s0 * 16 + q];
                    float4 v1 = h4[(size_t)s1 * 16 + q];
                    acc.x += v0.x + v1.x;
                    acc.y += v0.y + v1.y;
                    acc.z += v0.z + v1.z;
                    acc.w += v0.w + v1.w;
                }
                if (j + 1 < end) {
                    int s = d_col[j + half];
                    float4 v = h4[(size_t)s * 16 + q];
                    acc.x += v.x; acc.y += v.y; acc.z += v.z; acc.w += v.w;
                    j += 2;
                }
                if (j < end && half == 0) {
                    int s = d_col[j];
                    float4 v = h4[(size_t)s * 16 + q];
                    acc.x += v.x; acc.y += v.y; acc.z += v.z; acc.w += v.w;
                }
            }
            acc.x += __shfl_xor_sync(0xffffffffu, acc.x, 16);
            acc.y += __shfl_xor_sync(0xffffffffu, acc.y, 16);
            acc.z += __shfl_xor_sync(0xffffffffu, acc.z, 16);
            acc.w += __shfl_xor_sync(0xffffffffu, acc.w, 16);
            if (half == 0) {
                sAT[(4 * q + 0) * 68 + nodeL] = acc.x;
                sAT[(4 * q + 1) * 68 + nodeL] = acc.y;
                sAT[(4 * q + 2) * 68 + nodeL] = acc.z;
                sAT[(4 * q + 3) * 68 + nodeL] = acc.w;
            }
        }
    }
    __syncthreads();

    // ---- phase 1: x1 = relu(agg @ W1 + b1) -> sX transposed ----
    {
        int ng = tid & 15;
        int og = tid >> 4;
        float acc[4][8];
#pragma unroll
        for (int i = 0; i < 4; i++)
#pragma unroll
            for (int j = 0; j < 8; j++) acc[i][j] = 0.f;

#pragma unroll
        for (int k = 0; k < D; k++) {
            float4 a4 = *(const float4*)&sAT[k * 68 + ng * 4];
            float av[4] = {a4.x, a4.y, a4.z, a4.w};
            float4 w0 = *(const float4*)&sW1[k * HID + og * 8];
            float4 w1 = *(const float4*)&sW1[k * HID + og * 8 + 4];
            float wv[8] = {w0.x, w0.y, w0.z, w0.w, w1.x, w1.y, w1.z, w1.w};
#pragma unroll
            for (int i = 0; i < 4; i++)
#pragma unroll
                for (int j = 0; j < 8; j++) acc[i][j] += av[i] * wv[j];
        }
        float bb[8];
#pragma unroll
        for (int j = 0; j < 8; j++) bb[j] = b1[og * 8 + j];
#pragma unroll
        for (int i = 0; i < 4; i++)
#pragma unroll
            for (int j = 0; j < 8; j++)
                sX[(og * 8 + j) * 68 + (ng * 4 + i)] = fmaxf(acc[i][j] + bb[j], 0.f);
    }
    __syncthreads();

    // ---- phase 2: y = x1 @ W2 ; 4 nodes x 5 outs, 2-way k-split ----
    {
        int ks = tid >> 7;        // k half: 0 -> k[0,64), 1 -> k[64,128)
        int r  = tid & 127;
        int ng = r >> 3;          // nodes ng*4 .. +3
        int og = r & 7;           // outs  og*5 .. +4
        float acc[4][5];
#pragma unroll
        for (int i = 0; i < 4; i++)
#pragma unroll
            for (int j = 0; j < 5; j++) acc[i][j] = 0.f;

        int kbase = ks * 64;
#pragma unroll 8
        for (int kk = 0; kk < 64; kk++) {
            int k = kbase + kk;
            float4 a4 = *(const float4*)&sX[k * 68 + ng * 4];
            float av[4] = {a4.x, a4.y, a4.z, a4.w};
            float wv[5];
#pragma unroll
            for (int j = 0; j < 5; j++) wv[j] = sW2[k * C + og * 5 + j];
#pragma unroll
            for (int i = 0; i < 4; i++)
#pragma unroll
                for (int j = 0; j < 5; j++) acc[i][j] += av[i] * wv[j];
        }

        // reduce the two k-halves through (dead) sAT region, stride 21 = conflict-free
        float* sRed = smem + SM_AT;
        if (ks == 1) {
#pragma unroll
            for (int i = 0; i < 4; i++)
#pragma unroll
                for (int j = 0; j < 5; j++)
                    sRed[r * 21 + i * 5 + j] = acc[i][j];
        }
        __syncthreads();
        if (ks == 0) {
#pragma unroll
            for (int i = 0; i < 4; i++) {
                int gn = node0 + ng * 4 + i;
                if (gn < n) {
#pragma unroll
                    for (int j = 0; j < 5; j++)
                        d_y[(size_t)gn * C + og * 5 + j] =
                            acc[i][j] + sRed[r * 21 + i * 5 + j];
                }
            }
        }
    }
}

// ---------------- layer-2 aggregation + bias + softmax ----------------
__global__ void k_agg2_softmax(const float* __restrict__ b2, float* __restrict__ out, int n) {
    int w = (blockIdx.x * blockDim.x + threadIdx.x) >> 5;
    int lane = threadIdx.x & 31;
    if (w >= n) return;

    int g = lane / 10;
    int q = lane - g * 10;
    bool act = (lane < 30);
    const float4* Y4 = (const float4*)d_y;

    float4 acc = make_float4(0.f, 0.f, 0.f, 0.f);
    if (act && g == 0) acc = Y4[(size_t)w * 10 + q];

    int beg = d_rowptr[w], end = d_rowptr[w + 1];
    int j = beg;
    for (; j + 5 < end; j += 6) {
        if (act) {
            int s0 = d_col[j + g];
            int s1 = d_col[j + 3 + g];
            float4 v0 = Y4[(size_t)s0 * 10 + q];
            float4 v1 = Y4[(size_t)s1 * 10 + q];
            acc.x += v0.x + v1.x;
            acc.y += v0.y + v1.y;
            acc.z += v0.z + v1.z;
            acc.w += v0.w + v1.w;
        }
    }
    if (j + 2 < end) {
        if (act) {
            int s = d_col[j + g];
            float4 v = Y4[(size_t)s * 10 + q];
            acc.x += v.x; acc.y += v.y; acc.z += v.z; acc.w += v.w;
        }
        j += 3;
    }
    int rem = end - j;
    if (act && g < rem) {
        int s = d_col[j + g];
        float4 v = Y4[(size_t)s * 10 + q];
        acc.x += v.x; acc.y += v.y; acc.z += v.z; acc.w += v.w;
    }

    acc.x += __shfl_sync(0xffffffffu, acc.x, lane + 10) + __shfl_sync(0xffffffffu, acc.x, lane + 20);
    acc.y += __shfl_sync(0xffffffffu, acc.y, lane + 10) + __shfl_sync(0xffffffffu, acc.y, lane + 20);
    acc.z += __shfl_sync(0xffffffffu, acc.z, lane + 10) + __shfl_sync(0xffffffffu, acc.z, lane + 20);
    acc.w += __shfl_sync(0xffffffffu, acc.w, lane + 10) + __shfl_sync(0xffffffffu, acc.w, lane + 20);

    bool own = (lane < 10);
    if (own) {
        acc.x += b2[lane * 4 + 0];
        acc.y += b2[lane * 4 + 1];
        acc.z += b2[lane * 4 + 2];
        acc.w += b2[lane * 4 + 3];
    }
    float m = own ? fmaxf(fmaxf(acc.x, acc.y), fmaxf(acc.z, acc.w)) : -1e30f;
#pragma unroll
    for (int off = 16; off; off >>= 1)
        m = fmaxf(m, __shfl_xor_sync(0xffffffffu, m, off));
    float e0 = __expf(acc.x - m);
    float e1 = __expf(acc.y - m);
    float e2 = __expf(acc.z - m);
    float e3 = __expf(acc.w - m);
    float s = own ? (e0 + e1) + (e2 + e3) : 0.f;
#pragma unroll
    for (int off = 16; off; off >>= 1)
        s += __shfl_xor_sync(0xffffffffu, s, off);
    float inv = 1.f / s;
    if (own) {
        float* o = out + (size_t)w * C + lane * 4;
        o[0] = e0 * inv;
        o[1] = e1 * inv;
        o[2] = e2 * inv;
        o[3] = e3 * inv;
    }
}

// ---------------- launch ----------------
extern "C" void kernel_launch(void* const* d_in, const int* in_sizes, int n_in,
                              void* d_out, int out_size) {
    const float* h   = (const float*)d_in[0];
    const int*   adj = (const int*)d_in[1];
    const float* W1  = (const float*)d_in[2];
    const float* b1  = (const float*)d_in[3];
    const float* W2  = (const float*)d_in[4];
    const float* b2  = (const float*)d_in[5];
    float* out = (float*)d_out;

    int n = in_sizes[0] / D;
    int e = in_sizes[1] / 2;
    if (n > MAXN) n = MAXN;
    if (e > MAXE) e = MAXE;
    int nb = (n + 255) / 256;

    cudaFuncSetAttribute(k_fused, cudaFuncAttributeMaxDynamicSharedMemorySize,
                         SM_TOTAL_F * (int)sizeof(float));

    k_init<<<(n + 255) / 256, 256>>>(n);
    k_count<<<(e + 255) / 256, 256>>>((const int2*)adj, e);
    k_scan1<<<nb, 256>>>(n);
    k_scan2<<<1, 512>>>(nb, n);
    k_scan3<<<nb, 256>>>(n);
    k_scatter<<<(e + 255) / 256, 256>>>((const int2*)adj, e);

    k_fused<<<(n + 63) / 64, 256, SM_TOTAL_F * sizeof(float)>>>(h, W1, b1, W2, n);
    k_agg2_softmax<<<(n * 32 + 255) / 256, 256>>>(b2, out, n);
}

// round 9
// speedup vs baseline: 1.1642x; 1.0527x over previous
#include <cuda_runtime.h>
#include <cuda_bf16.h>
#include <math.h>

#define MAXN 100000
#define MAXE 1200000
#define D    64
#define HID  128
#define C    40
#define CAP  128      // per-node edge bucket capacity; P(Poisson(12) >= 128) ~ 1e-80

// ---------------- device scratch ----------------
__device__ int   d_deg[MAXN];
__device__ int   d_colb[(size_t)MAXN * CAP];      // 51.2 MB bucket array
__device__ __align__(16) float d_y[(size_t)MAXN * C];

// ---------------- build: count + bucket-scatter in one pass ----------------
__global__ void k_init(int n) {
    int i = blockIdx.x * blockDim.x + threadIdx.x;
    if (i < n) d_deg[i] = 0;
}

__global__ void k_build(const int2* __restrict__ adj, int e) {
    int i = blockIdx.x * blockDim.x + threadIdx.x;
    if (i < e) {
        int2 ed = adj[i];
        int p = atomicAdd(&d_deg[ed.y], 1);
        d_colb[(size_t)ed.y * CAP + p] = ed.x;
    }
}

// ---------------- fused: agg1 + GEMM1 + ReLU + GEMM2 -> d_y ----------------
// smem floats: sW1[64*128]=8192 | sW2[128*40]=5120 | sAT[64][68]=4352 | sX[128][68]=8704
#define SM_W1 0
#define SM_W2 8192
#define SM_AT 13312
#define SM_X  17664
#define SM_TOTAL_F 26368   // 105472 bytes

__global__ void __launch_bounds__(256) k_fused(const float* __restrict__ h,
                                               const float* __restrict__ W1,
                                               const float* __restrict__ b1,
                                               const float* __restrict__ W2,
                                               int n) {
    extern __shared__ float smem[];
    float* sW1 = smem + SM_W1;
    float* sW2 = smem + SM_W2;
    float* sAT = smem + SM_AT;   // [k][node] stride 68 (16B rows)
    float* sX  = smem + SM_X;    // [hid][node] stride 68 (16B rows)

    int tid = threadIdx.x;
    int node0 = blockIdx.x * 64;

    {
        const float4* W4 = (const float4*)W1;
        float4* s4 = (float4*)sW1;
#pragma unroll
        for (int i = 0; i < 8; i++) s4[tid + i * 256] = W4[tid + i * 256];
        const float4* V4 = (const float4*)W2;
        float4* t4 = (float4*)sW2;
#pragma unroll
        for (int i = 0; i < 5; i++) t4[tid + i * 256] = V4[tid + i * 256];
    }

    // ---- phase 0: gather-aggregate; half-warp x float4 ----
    {
        int w = tid >> 5, lane = tid & 31;
        int half = lane >> 4;
        int q = lane & 15;
        const float4* h4 = (const float4*)h;
#pragma unroll
        for (int ii = 0; ii < 8; ii++) {
            int nodeL = w * 8 + ii;
            int gn = node0 + nodeL;
            float4 acc = make_float4(0.f, 0.f, 0.f, 0.f);
            if (gn < n) {
                if (half == 0) acc = h4[(size_t)gn * 16 + q];   // self-loop
                const int* col = d_colb + (size_t)gn * CAP;
                int end = d_deg[gn];
                int j = 0;
                for (; j + 3 < end; j += 4) {
                    int s0 = col[j + half];
                    int s1 = col[j + 2 + half];
                    float4 v0 = h4[(size_t)s0 * 16 + q];
                    float4 v1 = h4[(size_t)s1 * 16 + q];
                    acc.x += v0.x + v1.x;
                    acc.y += v0.y + v1.y;
                    acc.z += v0.z + v1.z;
                    acc.w += v0.w + v1.w;
                }
                if (j + 1 < end) {
                    int s = col[j + half];
                    float4 v = h4[(size_t)s * 16 + q];
                    acc.x += v.x; acc.y += v.y; acc.z += v.z; acc.w += v.w;
                    j += 2;
                }
                if (j < end && half == 0) {
                    int s = col[j];
                    float4 v = h4[(size_t)s * 16 + q];
                    acc.x += v.x; acc.y += v.y; acc.z += v.z; acc.w += v.w;
                }
            }
            acc.x += __shfl_xor_sync(0xffffffffu, acc.x, 16);
            acc.y += __shfl_xor_sync(0xffffffffu, acc.y, 16);
            acc.z += __shfl_xor_sync(0xffffffffu, acc.z, 16);
            acc.w += __shfl_xor_sync(0xffffffffu, acc.w, 16);
            if (half == 0) {
                sAT[(4 * q + 0) * 68 + nodeL] = acc.x;
                sAT[(4 * q + 1) * 68 + nodeL] = acc.y;
                sAT[(4 * q + 2) * 68 + nodeL] = acc.z;
                sAT[(4 * q + 3) * 68 + nodeL] = acc.w;
            }
        }
    }
    __syncthreads();

    // ---- phase 1: x1 = relu(agg @ W1 + b1) -> sX transposed ----
    {
        int ng = tid & 15;
        int og = tid >> 4;
        float acc[4][8];
#pragma unroll
        for (int i = 0; i < 4; i++)
#pragma unroll
            for (int j = 0; j < 8; j++) acc[i][j] = 0.f;

#pragma unroll
        for (int k = 0; k < D; k++) {
            float4 a4 = *(const float4*)&sAT[k * 68 + ng * 4];
            float av[4] = {a4.x, a4.y, a4.z, a4.w};
            float4 w0 = *(const float4*)&sW1[k * HID + og * 8];
            float4 w1 = *(const float4*)&sW1[k * HID + og * 8 + 4];
            float wv[8] = {w0.x, w0.y, w0.z, w0.w, w1.x, w1.y, w1.z, w1.w};
#pragma unroll
            for (int i = 0; i < 4; i++)
#pragma unroll
                for (int j = 0; j < 8; j++) acc[i][j] += av[i] * wv[j];
        }
        float bb[8];
#pragma unroll
        for (int j = 0; j < 8; j++) bb[j] = b1[og * 8 + j];
#pragma unroll
        for (int i = 0; i < 4; i++)
#pragma unroll
            for (int j = 0; j < 8; j++)
                sX[(og * 8 + j) * 68 + (ng * 4 + i)] = fmaxf(acc[i][j] + bb[j], 0.f);
    }
    __syncthreads();

    // ---- phase 2: y = x1 @ W2 ; 4 nodes x 5 outs, 2-way k-split ----
    {
        int ks = tid >> 7;
        int r  = tid & 127;
        int ng = r >> 3;
        int og = r & 7;
        float acc[4][5];
#pragma unroll
        for (int i = 0; i < 4; i++)
#pragma unroll
            for (int j = 0; j < 5; j++) acc[i][j] = 0.f;

        int kbase = ks * 64;
#pragma unroll 8
        for (int kk = 0; kk < 64; kk++) {
            int k = kbase + kk;
            float4 a4 = *(const float4*)&sX[k * 68 + ng * 4];
            float av[4] = {a4.x, a4.y, a4.z, a4.w};
            float wv[5];
#pragma unroll
            for (int j = 0; j < 5; j++) wv[j] = sW2[k * C + og * 5 + j];
#pragma unroll
            for (int i = 0; i < 4; i++)
#pragma unroll
                for (int j = 0; j < 5; j++) acc[i][j] += av[i] * wv[j];
        }

        float* sRed = smem + SM_AT;   // dead sAT region
        if (ks == 1) {
#pragma unroll
            for (int i = 0; i < 4; i++)
#pragma unroll
                for (int j = 0; j < 5; j++)
                    sRed[r * 21 + i * 5 + j] = acc[i][j];
        }
        __syncthreads();
        if (ks == 0) {
#pragma unroll
            for (int i = 0; i < 4; i++) {
                int gn = node0 + ng * 4 + i;
                if (gn < n) {
#pragma unroll
                    for (int j = 0; j < 5; j++)
                        d_y[(size_t)gn * C + og * 5 + j] =
                            acc[i][j] + sRed[r * 21 + i * 5 + j];
                }
            }
        }
    }
}

// ---------------- layer-2 aggregation + bias + softmax ----------------
__global__ void k_agg2_softmax(const float* __restrict__ b2, float* __restrict__ out, int n) {
    int w = (blockIdx.x * blockDim.x + threadIdx.x) >> 5;
    int lane = threadIdx.x & 31;
    if (w >= n) return;

    int g = lane / 10;
    int q = lane - g * 10;
    bool act = (lane < 30);
    const float4* Y4 = (const float4*)d_y;

    float4 acc = make_float4(0.f, 0.f, 0.f, 0.f);
    if (act && g == 0) acc = Y4[(size_t)w * 10 + q];

    const int* col = d_colb + (size_t)w * CAP;
    int end = d_deg[w];
    int j = 0;
    for (; j + 5 < end; j += 6) {
        if (act) {
            int s0 = col[j + g];
            int s1 = col[j + 3 + g];
            float4 v0 = Y4[(size_t)s0 * 10 + q];
            float4 v1 = Y4[(size_t)s1 * 10 + q];
            acc.x += v0.x + v1.x;
            acc.y += v0.y + v1.y;
            acc.z += v0.z + v1.z;
            acc.w += v0.w + v1.w;
        }
    }
    if (j + 2 < end) {
        if (act) {
            int s = col[j + g];
            float4 v = Y4[(size_t)s * 10 + q];
            acc.x += v.x; acc.y += v.y; acc.z += v.z; acc.w += v.w;
        }
        j += 3;
    }
    int rem = end - j;
    if (act && g < rem) {
        int s = col[j + g];
        float4 v = Y4[(size_t)s * 10 + q];
        acc.x += v.x; acc.y += v.y; acc.z += v.z; acc.w += v.w;
    }

    acc.x += __shfl_sync(0xffffffffu, acc.x, lane + 10) + __shfl_sync(0xffffffffu, acc.x, lane + 20);
    acc.y += __shfl_sync(0xffffffffu, acc.y, lane + 10) + __shfl_sync(0xffffffffu, acc.y, lane + 20);
    acc.z += __shfl_sync(0xffffffffu, acc.z, lane + 10) + __shfl_sync(0xffffffffu, acc.z, lane + 20);
    acc.w += __shfl_sync(0xffffffffu, acc.w, lane + 10) + __shfl_sync(0xffffffffu, acc.w, lane + 20);

    bool own = (lane < 10);
    if (own) {
        acc.x += b2[lane * 4 + 0];
        acc.y += b2[lane * 4 + 1];
        acc.z += b2[lane * 4 + 2];
        acc.w += b2[lane * 4 + 3];
    }
    float m = own ? fmaxf(fmaxf(acc.x, acc.y), fmaxf(acc.z, acc.w)) : -1e30f;
#pragma unroll
    for (int off = 16; off; off >>= 1)
        m = fmaxf(m, __shfl_xor_sync(0xffffffffu, m, off));
    float e0 = __expf(acc.x - m);
    float e1 = __expf(acc.y - m);
    float e2 = __expf(acc.z - m);
    float e3 = __expf(acc.w - m);
    float s = own ? (e0 + e1) + (e2 + e3) : 0.f;
#pragma unroll
    for (int off = 16; off; off >>= 1)
        s += __shfl_xor_sync(0xffffffffu, s, off);
    float inv = 1.f / s;
    if (own) {
        float* o = out + (size_t)w * C + lane * 4;
        o[0] = e0 * inv;
        o[1] = e1 * inv;
        o[2] = e2 * inv;
        o[3] = e3 * inv;
    }
}

// ---------------- launch ----------------
extern "C" void kernel_launch(void* const* d_in, const int* in_sizes, int n_in,
                              void* d_out, int out_size) {
    const float* h   = (const float*)d_in[0];
    const int*   adj = (const int*)d_in[1];
    const float* W1  = (const float*)d_in[2];
    const float* b1  = (const float*)d_in[3];
    const float* W2  = (const float*)d_in[4];
    const float* b2  = (const float*)d_in[5];
    float* out = (float*)d_out;

    int n = in_sizes[0] / D;
    int e = in_sizes[1] / 2;
    if (n > MAXN) n = MAXN;
    if (e > MAXE) e = MAXE;

    cudaFuncSetAttribute(k_fused, cudaFuncAttributeMaxDynamicSharedMemorySize,
                         SM_TOTAL_F * (int)sizeof(float));

    k_init<<<(n + 255) / 256, 256>>>(n);
    k_build<<<(e + 255) / 256, 256>>>((const int2*)adj, e);

    k_fused<<<(n + 63) / 64, 256, SM_TOTAL_F * sizeof(float)>>>(h, W1, b1, W2, n);
    k_agg2_softmax<<<(n * 32 + 255) / 256, 256>>>(b2, out, n);
}

// round 11
// speedup vs baseline: 1.2297x; 1.0563x over previous
#include <cuda_runtime.h>
#include <cuda_bf16.h>
#include <math.h>

#define MAXN 100000
#define MAXE 1200000
#define D    64
#define HID  128
#define C    40
#define CAP  128      // per-node bucket capacity; P(Poisson(12) >= 128) ~ 1e-80

// ---------------- device scratch ----------------
__device__ int   d_deg[MAXN];
__device__ int   d_colb[(size_t)MAXN * CAP];      // 51.2 MB bucket array
__device__ __align__(16) float d_y[(size_t)MAXN * C];

// ---------------- build: count + bucket-scatter in one pass ----------------
__global__ void k_init(int n) {
    int i = blockIdx.x * blockDim.x + threadIdx.x;
    if (i < n) d_deg[i] = 0;
}

__global__ void k_build(const int2* __restrict__ adj, int e) {
    int i = blockIdx.x * blockDim.x + threadIdx.x;
    if (i < e) {
        int2 ed = adj[i];
        int p = atomicAdd(&d_deg[ed.y], 1);
        d_colb[ed.y * CAP + p] = ed.x;
    }
}

// ---------------- fused: agg1 + GEMM1 + ReLU + GEMM2 -> d_y ----------------
// smem floats: sW1[64*128]=8192 | sW2[128*40]=5120 | sAT[64][68]=4352 | sX[128][68]=8704
#define SM_W1 0
#define SM_W2 8192
#define SM_AT 13312
#define SM_X  17664
#define SM_TOTAL_F 26368   // 105472 bytes

__global__ void __launch_bounds__(256) k_fused(const float* __restrict__ h,
                                               const float* __restrict__ W1,
                                               const float* __restrict__ b1,
                                               const float* __restrict__ W2,
                                               int n) {
    extern __shared__ float smem[];
    float* sW1 = smem + SM_W1;
    float* sW2 = smem + SM_W2;
    float* sAT = smem + SM_AT;   // [k][node] stride 68 (16B rows)
    float* sX  = smem + SM_X;    // [hid][node] stride 68 (16B rows)

    int tid = threadIdx.x;
    int node0 = blockIdx.x * 64;

    {
        const float4* W4 = (const float4*)W1;
        float4* s4 = (float4*)sW1;
#pragma unroll
        for (int i = 0; i < 8; i++) s4[tid + i * 256] = W4[tid + i * 256];
        const float4* V4 = (const float4*)W2;
        float4* t4 = (float4*)sW2;
#pragma unroll
        for (int i = 0; i < 5; i++) t4[tid + i * 256] = V4[tid + i * 256];
    }

    // ---- phase 0: gather-aggregate; half-warp x float4, 8 edges/main step ----
    {
        int w = tid >> 5, lane = tid & 31;
        int half = lane >> 4;
        int q = lane & 15;
        const float4* h4 = (const float4*)h;
#pragma unroll
        for (int ii = 0; ii < 8; ii++) {
            int nodeL = w * 8 + ii;
            int gn = node0 + nodeL;
            float4 acc = make_float4(0.f, 0.f, 0.f, 0.f);
            if (gn < n) {
                if (half == 0) acc = h4[gn * 16 + q];   // self-loop
                const int* col = d_colb + gn * CAP;
                int end = d_deg[gn];
                int j = 0;
                for (; j + 7 < end; j += 8) {            // 8 edges, 4 loads/half
                    int s0 = col[j + half];
                    int s1 = col[j + 2 + half];
                    int s2 = col[j + 4 + half];
                    int s3 = col[j + 6 + half];
                    float4 v0 = h4[s0 * 16 + q];
                    float4 v1 = h4[s1 * 16 + q];
                    float4 v2 = h4[s2 * 16 + q];
                    float4 v3 = h4[s3 * 16 + q];
                    acc.x += (v0.x + v1.x) + (v2.x + v3.x);
                    acc.y += (v0.y + v1.y) + (v2.y + v3.y);
                    acc.z += (v0.z + v1.z) + (v2.z + v3.z);
                    acc.w += (v0.w + v1.w) + (v2.w + v3.w);
                }
                if (j + 3 < end) {                       // 4 edges
                    int s0 = col[j + half];
                    int s1 = col[j + 2 + half];
                    float4 v0 = h4[s0 * 16 + q];
                    float4 v1 = h4[s1 * 16 + q];
                    acc.x += v0.x + v1.x;
                    acc.y += v0.y + v1.y;
                    acc.z += v0.z + v1.z;
                    acc.w += v0.w + v1.w;
                    j += 4;
                }
                if (j + 1 < end) {                       // 2 edges
                    int s = col[j + half];
                    float4 v = h4[s * 16 + q];
                    acc.x += v.x; acc.y += v.y; acc.z += v.z; acc.w += v.w;
                    j += 2;
                }
                if (j < end && half == 0) {              // last odd edge
                    int s = col[j];
                    float4 v = h4[s * 16 + q];
                    acc.x += v.x; acc.y += v.y; acc.z += v.z; acc.w += v.w;
                }
            }
            acc.x += __shfl_xor_sync(0xffffffffu, acc.x, 16);
            acc.y += __shfl_xor_sync(0xffffffffu, acc.y, 16);
            acc.z += __shfl_xor_sync(0xffffffffu, acc.z, 16);
            acc.w += __shfl_xor_sync(0xffffffffu, acc.w, 16);
            if (half == 0) {
                sAT[(4 * q + 0) * 68 + nodeL] = acc.x;
                sAT[(4 * q + 1) * 68 + nodeL] = acc.y;
                sAT[(4 * q + 2) * 68 + nodeL] = acc.z;
                sAT[(4 * q + 3) * 68 + nodeL] = acc.w;
            }
        }
    }
    __syncthreads();

    // ---- phase 1: x1 = relu(agg @ W1 + b1) -> sX transposed ----
    {
        int ng = tid & 15;
        int og = tid >> 4;
        float acc[4][8];
#pragma unroll
        for (int i = 0; i < 4; i++)
#pragma unroll
            for (int j = 0; j < 8; j++) acc[i][j] = 0.f;

#pragma unroll
        for (int k = 0; k < D; k++) {
            float4 a4 = *(const float4*)&sAT[k * 68 + ng * 4];
            float av[4] = {a4.x, a4.y, a4.z, a4.w};
            float4 w0 = *(const float4*)&sW1[k * HID + og * 8];
            float4 w1 = *(const float4*)&sW1[k * HID + og * 8 + 4];
            float wv[8] = {w0.x, w0.y, w0.z, w0.w, w1.x, w1.y, w1.z, w1.w};
#pragma unroll
            for (int i = 0; i < 4; i++)
#pragma unroll
                for (int j = 0; j < 8; j++) acc[i][j] += av[i] * wv[j];
        }
        float bb[8];
#pragma unroll
        for (int j = 0; j < 8; j++) bb[j] = b1[og * 8 + j];
#pragma unroll
        for (int i = 0; i < 4; i++)
#pragma unroll
            for (int j = 0; j < 8; j++)
                sX[(og * 8 + j) * 68 + (ng * 4 + i)] = fmaxf(acc[i][j] + bb[j], 0.f);
    }
    __syncthreads();

    // ---- phase 2: y = x1 @ W2 ; 4 nodes x 5 outs, 2-way k-split ----
    {
        int ks = tid >> 7;
        int r  = tid & 127;
        int ng = r >> 3;
        int og = r & 7;
        float acc[4][5];
#pragma unroll
        for (int i = 0; i < 4; i++)
#pragma unroll
            for (int j = 0; j < 5; j++) acc[i][j] = 0.f;

        int kbase = ks * 64;
#pragma unroll 8
        for (int kk = 0; kk < 64; kk++) {
            int k = kbase + kk;
            float4 a4 = *(const float4*)&sX[k * 68 + ng * 4];
            float av[4] = {a4.x, a4.y, a4.z, a4.w};
            float wv[5];
#pragma unroll
            for (int j = 0; j < 5; j++) wv[j] = sW2[k * C + og * 5 + j];
#pragma unroll
            for (int i = 0; i < 4; i++)
#pragma unroll
                for (int j = 0; j < 5; j++) acc[i][j] += av[i] * wv[j];
        }

        float* sRed = smem + SM_AT;   // dead sAT region
        if (ks == 1) {
#pragma unroll
            for (int i = 0; i < 4; i++)
#pragma unroll
                for (int j = 0; j < 5; j++)
                    sRed[r * 21 + i * 5 + j] = acc[i][j];
        }
        __syncthreads();
        if (ks == 0) {
#pragma unroll
            for (int i = 0; i < 4; i++) {
                int gn = node0 + ng * 4 + i;
                if (gn < n) {
#pragma unroll
                    for (int j = 0; j < 5; j++)
                        d_y[gn * C + og * 5 + j] =
                            acc[i][j] + sRed[r * 21 + i * 5 + j];
                }
            }
        }
    }
}

// ---------------- layer-2 aggregation + bias + softmax (12 edges/main step) ----------------
__global__ void k_agg2_softmax(const float* __restrict__ b2, float* __restrict__ out, int n) {
    int w = (blockIdx.x * blockDim.x + threadIdx.x) >> 5;
    int lane = threadIdx.x & 31;
    if (w >= n) return;

    int g = lane / 10;            // edge group 0..2 (lanes 30,31 idle)
    int q = lane - g * 10;        // float4 slot 0..9
    bool act = (lane < 30);
    const float4* Y4 = (const float4*)d_y;

    float4 acc = make_float4(0.f, 0.f, 0.f, 0.f);
    if (act && g == 0) acc = Y4[w * 10 + q];     // self-loop

    const int* col = d_colb + w * CAP;
    int end = d_deg[w];
    int j = 0;
    for (; j + 11 < end; j += 12) {              // 12 edges, 4 loads in flight/lane
        if (act) {
            int s0 = col[j + g];
            int s1 = col[j + 3 + g];
            int s2 = col[j + 6 + g];
            int s3 = col[j + 9 + g];
            float4 v0 = Y4[s0 * 10 + q];
            float4 v1 = Y4[s1 * 10 + q];
            float4 v2 = Y4[s2 * 10 + q];
            float4 v3 = Y4[s3 * 10 + q];
            acc.x += (v0.x + v1.x) + (v2.x + v3.x);
            acc.y += (v0.y + v1.y) + (v2.y + v3.y);
            acc.z += (v0.z + v1.z) + (v2.z + v3.z);
            acc.w += (v0.w + v1.w) + (v2.w + v3.w);
        }
    }
    if (j + 5 < end) {                           // 6 edges
        if (act) {
            int s0 = col[j + g];
            int s1 = col[j + 3 + g];
            float4 v0 = Y4[s0 * 10 + q];
            float4 v1 = Y4[s1 * 10 + q];
            acc.x += v0.x + v1.x;
            acc.y += v0.y + v1.y;
            acc.z += v0.z + v1.z;
            acc.w += v0.w + v1.w;
        }
        j += 6;
    }
    if (j + 2 < end) {                           // 3 edges
        if (act) {
            int s = col[j + g];
            float4 v = Y4[s * 10 + q];
            acc.x += v.x; acc.y += v.y; acc.z += v.z; acc.w += v.w;
        }
        j += 3;
    }
    int rem = end - j;                           // 0..2 edges
    if (act && g < rem) {
        int s = col[j + g];
        float4 v = Y4[s * 10 + q];
        acc.x += v.x; acc.y += v.y; acc.z += v.z; acc.w += v.w;
    }

    // merge 3 groups into lanes 0-9
    acc.x += __shfl_sync(0xffffffffu, acc.x, lane + 10) + __shfl_sync(0xffffffffu, acc.x, lane + 20);
    acc.y += __shfl_sync(0xffffffffu, acc.y, lane + 10) + __shfl_sync(0xffffffffu, acc.y, lane + 20);
    acc.z += __shfl_sync(0xffffffffu, acc.z, lane + 10) + __shfl_sync(0xffffffffu, acc.z, lane + 20);
    acc.w += __shfl_sync(0xffffffffu, acc.w, lane + 10) + __shfl_sync(0xffffffffu, acc.w, lane + 20);

    bool own = (lane < 10);
    if (own) {
        acc.x += b2[lane * 4 + 0];
        acc.y += b2[lane * 4 + 1];
        acc.z += b2[lane * 4 + 2];
        acc.w += b2[lane * 4 + 3];
    }
    float m = own ? fmaxf(fmaxf(acc.x, acc.y), fmaxf(acc.z, acc.w)) : -1e30f;
#pragma unroll
    for (int off = 16; off; off >>= 1)
        m = fmaxf(m, __shfl_xor_sync(0xffffffffu, m, off));
    float e0 = __expf(acc.x - m);
    float e1 = __expf(acc.y - m);
    float e2 = __expf(acc.z - m);
    float e3 = __expf(acc.w - m);
    float s = own ? (e0 + e1) + (e2 + e3) : 0.f;
#pragma unroll
    for (int off = 16; off; off >>= 1)
        s += __shfl_xor_sync(0xffffffffu, s, off);
    float inv = 1.f / s;
    if (own) {
        float* o = out + w * C + lane * 4;
        o[0] = e0 * inv;
        o[1] = e1 * inv;
        o[2] = e2 * inv;
        o[3] = e3 * inv;
    }
}

// ---------------- launch ----------------
extern "C" void kernel_launch(void* const* d_in, const int* in_sizes, int n_in,
                              void* d_out, int out_size) {
    const float* h   = (const float*)d_in[0];
    const int*   adj = (const int*)d_in[1];
    const float* W1  = (const float*)d_in[2];
    const float* b1  = (const float*)d_in[3];
    const float* W2  = (const float*)d_in[4];
    const float* b2  = (const float*)d_in[5];
    float* out = (float*)d_out;

    int n = in_sizes[0] / D;
    int e = in_sizes[1] / 2;
    if (n > MAXN) n = MAXN;
    if (e > MAXE) e = MAXE;

    cudaFuncSetAttribute(k_fused, cudaFuncAttributeMaxDynamicSharedMemorySize,
                         SM_TOTAL_F * (int)sizeof(float));

    k_init<<<(n + 255) / 256, 256>>>(n);
    k_build<<<(e + 255) / 256, 256>>>((const int2*)adj, e);

    k_fused<<<(n + 63) / 64, 256, SM_TOTAL_F * sizeof(float)>>>(h, W1, b1, W2, n);
    k_agg2_softmax<<<(n * 32 + 255) / 256, 256>>>(b2, out, n);
}

// round 12
// speedup vs baseline: 1.2759x; 1.0375x over previous
#include <cuda_runtime.h>
#include <cuda_bf16.h>
#include <math.h>
#include <cstdint>

#define MAXN 100000
#define MAXE 1200000
#define D    64
#define HID  128
#define C    40
#define CAP  128      // per-node bucket capacity; P(Poisson(12) >= 128) ~ 1e-80

// ---------------- device scratch ----------------
__device__ int   d_deg[MAXN];
__device__ int   d_colb[(size_t)MAXN * CAP];
__device__ __align__(16) float d_y[(size_t)MAXN * C];

// ---------------- tf32 helpers ----------------
__device__ __forceinline__ uint32_t f2tf32(float x) {
    uint32_t r;
    asm("cvt.rna.tf32.f32 %0, %1;" : "=r"(r) : "f"(x));
    return r;
}
#define MMA_TF32(cc, a0, a1, a2, a3, b0, b1) \
    asm volatile("mma.sync.aligned.m16n8k8.row.col.f32.tf32.tf32.f32 " \
        "{%0,%1,%2,%3}, {%4,%5,%6,%7}, {%8,%9}, {%0,%1,%2,%3};" \
        : "+f"((cc)[0]), "+f"((cc)[1]), "+f"((cc)[2]), "+f"((cc)[3]) \
        : "r"(a0), "r"(a1), "r"(a2), "r"(a3), "r"(b0), "r"(b1))

// ---------------- build ----------------
__global__ void k_init(int n) {
    int i = blockIdx.x * blockDim.x + threadIdx.x;
    if (i < n) d_deg[i] = 0;
}

__global__ void k_build(const int2* __restrict__ adj, int e) {
    int i = blockIdx.x * blockDim.x + threadIdx.x;
    if (i < e) {
        int2 ed = adj[i];
        int p = atomicAdd(&d_deg[ed.y], 1);
        d_colb[ed.y * CAP + p] = ed.x;
    }
}

// ---------------- fused: agg1 + TF32 mma GEMM1 + ReLU + TF32 mma GEMM2 ----------------
// smem layout (word offsets):
// phase 0/1: SA_HI 0 [64x68] | SA_LO 4352 [64x68] | W1_HI 8704 [64x136] | W1_LO 17408 [64x136] (end 26112)
// phase 2  : X_HI 0 [64x132] | X_LO 8448 [64x132] | W2_HI 16896 [128x40] | W2_LO 22016 [128x40] (end 27136)
//            reduce scratch SC at 0 [64x44] after X reads complete
#define WO_SA_HI 0
#define WO_SA_LO 4352
#define WO_W1_HI 8704
#define WO_W1_LO 17408
#define WO_X_HI  0
#define WO_X_LO  8448
#define WO_W2_HI 16896
#define WO_W2_LO 22016
#define SM_WORDS 27136
#define SM_BYTES (SM_WORDS * 4)   // 108544

__global__ void __launch_bounds__(256, 2) k_fused(const float* __restrict__ h,
                                                  const float* __restrict__ W1,
                                                  const float* __restrict__ b1,
                                                  const float* __restrict__ W2,
                                                  int n) {
    extern __shared__ uint32_t smw[];
    int tid = threadIdx.x;
    int w = tid >> 5, lane = tid & 31;
    int g = lane >> 2, tg = lane & 3;      // mma group / thread-in-group
    int node0 = blockIdx.x * 64;

    // ---- W1 split -> smem [k][136] hi/lo ----
    {
        uint32_t* WH = smw + WO_W1_HI;
        uint32_t* WL = smw + WO_W1_LO;
#pragma unroll
        for (int i = 0; i < 32; i++) {
            int idx = tid + i * 256;       // k = idx>>7, n = idx&127
            int k = idx >> 7, nn = idx & 127;
            float v = W1[idx];
            uint32_t hi = f2tf32(v);
            float lo = v - __uint_as_float(hi);
            WH[k * 136 + nn] = hi;
            WL[k * 136 + nn] = f2tf32(lo);
        }
    }

    // ---- phase 0: gather-aggregate into SA_HI as fp32 [node][68] ----
    {
        float* sA = (float*)(smw + WO_SA_HI);
        int half = lane >> 4;
        int q = lane & 15;
        const float4* h4 = (const float4*)h;
#pragma unroll
        for (int ii = 0; ii < 8; ii++) {
            int nodeL = w * 8 + ii;
            int gn = node0 + nodeL;
            float4 acc = make_float4(0.f, 0.f, 0.f, 0.f);
            if (gn < n) {
                if (half == 0) acc = h4[gn * 16 + q];   // self-loop
                const int* col = d_colb + gn * CAP;
                int end = d_deg[gn];
                int j = 0;
                for (; j + 7 < end; j += 8) {
                    int s0 = col[j + half];
                    int s1 = col[j + 2 + half];
                    int s2 = col[j + 4 + half];
                    int s3 = col[j + 6 + half];
                    float4 v0 = h4[s0 * 16 + q];
                    float4 v1 = h4[s1 * 16 + q];
                    float4 v2 = h4[s2 * 16 + q];
                    float4 v3 = h4[s3 * 16 + q];
                    acc.x += (v0.x + v1.x) + (v2.x + v3.x);
                    acc.y += (v0.y + v1.y) + (v2.y + v3.y);
                    acc.z += (v0.z + v1.z) + (v2.z + v3.z);
                    acc.w += (v0.w + v1.w) + (v2.w + v3.w);
                }
                if (j + 3 < end) {
                    int s0 = col[j + half];
                    int s1 = col[j + 2 + half];
                    float4 v0 = h4[s0 * 16 + q];
                    float4 v1 = h4[s1 * 16 + q];
                    acc.x += v0.x + v1.x;
                    acc.y += v0.y + v1.y;
                    acc.z += v0.z + v1.z;
                    acc.w += v0.w + v1.w;
                    j += 4;
                }
                if (j + 1 < end) {
                    int s = col[j + half];
                    float4 v = h4[s * 16 + q];
                    acc.x += v.x; acc.y += v.y; acc.z += v.z; acc.w += v.w;
                    j += 2;
                }
                if (j < end && half == 0) {
                    int s = col[j];
                    float4 v = h4[s * 16 + q];
                    acc.x += v.x; acc.y += v.y; acc.z += v.z; acc.w += v.w;
                }
            }
            acc.x += __shfl_xor_sync(0xffffffffu, acc.x, 16);
            acc.y += __shfl_xor_sync(0xffffffffu, acc.y, 16);
            acc.z += __shfl_xor_sync(0xffffffffu, acc.z, 16);
            acc.w += __shfl_xor_sync(0xffffffffu, acc.w, 16);
            if (half == 0)
                *(float4*)(sA + nodeL * 68 + q * 4) = acc;
        }
    }
    __syncthreads();

    // ---- split A in place: SA_HI fp32 -> tf32 hi (in place) + lo (SA_LO) ----
    {
        uint32_t* AH = smw + WO_SA_HI;
        uint32_t* AL = smw + WO_SA_LO;
#pragma unroll
        for (int i = 0; i < 16; i++) {
            int idx = tid + i * 256;       // node = idx>>6, k = idx&63
            int a = (idx >> 6) * 68 + (idx & 63);
            float v = __uint_as_float(AH[a]);
            uint32_t hi = f2tf32(v);
            float lo = v - __uint_as_float(hi);
            AH[a] = hi;
            AL[a] = f2tf32(lo);
        }
    }
    __syncthreads();

    // ---- phase 1: x1 = relu(A @ W1 + b1) via tf32 mma (2-split, 3 products) ----
    float c1[8][4];
    {
        const uint32_t* AH = smw + WO_SA_HI;
        const uint32_t* AL = smw + WO_SA_LO;
        const uint32_t* WH = smw + WO_W1_HI;
        const uint32_t* WL = smw + WO_W1_LO;
        int mt = w & 3;           // node tile (16 nodes)
        int nh = w >> 1 & 0;      // placeholder (avoid warning)
        (void)nh;
        int nhalf = w >> 2;       // n half (64 cols)
#pragma unroll
        for (int nt = 0; nt < 8; nt++)
#pragma unroll
            for (int i = 0; i < 4; i++) c1[nt][i] = 0.f;

#pragma unroll
        for (int kt = 0; kt < 8; kt++) {
            int ar = (mt * 16 + g) * 68 + kt * 8 + tg;
            uint32_t ah0 = AH[ar],           ah1 = AH[ar + 8 * 68];
            uint32_t ah2 = AH[ar + 4],       ah3 = AH[ar + 8 * 68 + 4];
            uint32_t al0 = AL[ar],           al1 = AL[ar + 8 * 68];
            uint32_t al2 = AL[ar + 4],       al3 = AL[ar + 8 * 68 + 4];
#pragma unroll
            for (int nt = 0; nt < 8; nt++) {
                int br = (kt * 8 + tg) * 136 + nhalf * 64 + nt * 8 + g;
                uint32_t bh0 = WH[br], bh1 = WH[br + 4 * 136];
                uint32_t bl0 = WL[br], bl1 = WL[br + 4 * 136];
                MMA_TF32(c1[nt], ah0, ah1, ah2, ah3, bh0, bh1);
                MMA_TF32(c1[nt], ah0, ah1, ah2, ah3, bl0, bl1);
                MMA_TF32(c1[nt], al0, al1, al2, al3, bh0, bh1);
            }
        }
    }
    __syncthreads();   // all reads of SA/W1 done -> safe to overlay X

    // ---- write x1 (bias+relu) as tf32 splits into X_HI/X_LO [node][132] ----
    {
        uint32_t* XH = smw + WO_X_HI;
        uint32_t* XL = smw + WO_X_LO;
        int mt = w & 3;
        int nhalf = w >> 2;
#pragma unroll
        for (int nt = 0; nt < 8; nt++) {
            int col = nhalf * 64 + nt * 8 + tg * 2;
            float2 bb = *(const float2*)&b1[col];
#pragma unroll
            for (int ip = 0; ip < 2; ip++) {
                int row = mt * 16 + g + ip * 8;
                float v0 = fmaxf(c1[nt][ip * 2 + 0] + bb.x, 0.f);
                float v1 = fmaxf(c1[nt][ip * 2 + 1] + bb.y, 0.f);
                uint32_t h0 = f2tf32(v0), h1 = f2tf32(v1);
                uint32_t l0 = f2tf32(v0 - __uint_as_float(h0));
                uint32_t l1 = f2tf32(v1 - __uint_as_float(h1));
                *(uint2*)&XH[row * 132 + col] = make_uint2(h0, h1);
                *(uint2*)&XL[row * 132 + col] = make_uint2(l0, l1);
            }
        }
    }
    // ---- W2 split from gmem (L2-hot) into overlaid region ----
    {
        uint32_t* WH = smw + WO_W2_HI;
        uint32_t* WL = smw + WO_W2_LO;
#pragma unroll
        for (int i = 0; i < 20; i++) {
            int idx = tid + i * 256;       // linear [k*40+n]
            float v = W2[idx];
            uint32_t hi = f2tf32(v);
            WH[idx] = hi;
            WL[idx] = f2tf32(v - __uint_as_float(hi));
        }
    }
    __syncthreads();

    // ---- phase 2: y = x1 @ W2 via tf32 mma; 2-way k-split across warp halves ----
    float c2[5][4];
    {
        const uint32_t* XH = smw + WO_X_HI;
        const uint32_t* XL = smw + WO_X_LO;
        const uint32_t* WH = smw + WO_W2_HI;
        const uint32_t* WL = smw + WO_W2_LO;
        int mt = w & 3;
        int kh = w >> 2;
#pragma unroll
        for (int nt = 0; nt < 5; nt++)
#pragma unroll
            for (int i = 0; i < 4; i++) c2[nt][i] = 0.f;

#pragma unroll
        for (int kt = 0; kt < 8; kt++) {
            int k0 = kh * 64 + kt * 8;
            int ar = (mt * 16 + g) * 132 + k0 + tg;
            uint32_t ah0 = XH[ar],     ah1 = XH[ar + 8 * 132];
            uint32_t ah2 = XH[ar + 4], ah3 = XH[ar + 8 * 132 + 4];
            uint32_t al0 = XL[ar],     al1 = XL[ar + 8 * 132];
            uint32_t al2 = XL[ar + 4], al3 = XL[ar + 8 * 132 + 4];
#pragma unroll
            for (int nt = 0; nt < 5; nt++) {
                int br = (k0 + tg) * 40 + nt * 8 + g;
                uint32_t bh0 = WH[br], bh1 = WH[br + 4 * 40];
                uint32_t bl0 = WL[br], bl1 = WL[br + 4 * 40];
                MMA_TF32(c2[nt], ah0, ah1, ah2, ah3, bh0, bh1);
                MMA_TF32(c2[nt], ah0, ah1, ah2, ah3, bl0, bl1);
                MMA_TF32(c2[nt], al0, al1, al2, al3, bh0, bh1);
            }
        }
    }
    __syncthreads();   // X/W2 reads done -> scratch overlay OK

    // ---- reduce k-halves and write y ----
    {
        float* SC = (float*)(smw + WO_X_HI);   // [64][44] scratch
        int mt = w & 3;
        int kh = w >> 2;
        if (kh == 1) {
#pragma unroll
            for (int nt = 0; nt < 5; nt++)
#pragma unroll
                for (int ip = 0; ip < 2; ip++) {
                    int row = mt * 16 + g + ip * 8;
                    int col = nt * 8 + tg * 2;
                    *(float2*)&SC[row * 44 + col] =
                        make_float2(c2[nt][ip * 2], c2[nt][ip * 2 + 1]);
                }
        }
        __syncthreads();
        if (kh == 0) {
#pragma unroll
            for (int nt = 0; nt < 5; nt++)
#pragma unroll
                for (int ip = 0; ip < 2; ip++) {
                    int row = mt * 16 + g + ip * 8;
                    int gn = node0 + row;
                    int col = nt * 8 + tg * 2;
                    float2 o = *(float2*)&SC[row * 44 + col];
                    o.x += c2[nt][ip * 2];
                    o.y += c2[nt][ip * 2 + 1];
                    if (gn < n) *(float2*)&d_y[gn * C + col] = o;
                }
        }
    }
}

// ---------------- layer-2 aggregation + bias + softmax (12 edges/main step) ----------------
__global__ void k_agg2_softmax(const float* __restrict__ b2, float* __restrict__ out, int n) {
    int w = (blockIdx.x * blockDim.x + threadIdx.x) >> 5;
    int lane = threadIdx.x & 31;
    if (w >= n) return;

    int g = lane / 10;
    int q = lane - g * 10;
    bool act = (lane < 30);
    const float4* Y4 = (const float4*)d_y;

    float4 acc = make_float4(0.f, 0.f, 0.f, 0.f);
    if (act && g == 0) acc = Y4[w * 10 + q];

    const int* col = d_colb + w * CAP;
    int end = d_deg[w];
    int j = 0;
    for (; j + 11 < end; j += 12) {
        if (act) {
            int s0 = col[j + g];
            int s1 = col[j + 3 + g];
            int s2 = col[j + 6 + g];
            int s3 = col[j + 9 + g];
            float4 v0 = Y4[s0 * 10 + q];
            float4 v1 = Y4[s1 * 10 + q];
            float4 v2 = Y4[s2 * 10 + q];
            float4 v3 = Y4[s3 * 10 + q];
            acc.x += (v0.x + v1.x) + (v2.x + v3.x);
            acc.y += (v0.y + v1.y) + (v2.y + v3.y);
            acc.z += (v0.z + v1.z) + (v2.z + v3.z);
            acc.w += (v0.w + v1.w) + (v2.w + v3.w);
        }
    }
    if (j + 5 < end) {
        if (act) {
            int s0 = col[j + g];
            int s1 = col[j + 3 + g];
            float4 v0 = Y4[s0 * 10 + q];
            float4 v1 = Y4[s1 * 10 + q];
            acc.x += v0.x + v1.x;
            acc.y += v0.y + v1.y;
            acc.z += v0.z + v1.z;
            acc.w += v0.w + v1.w;
        }
        j += 6;
    }
    if (j + 2 < end) {
        if (act) {
            int s = col[j + g];
            float4 v = Y4[s * 10 + q];
            acc.x += v.x; acc.y += v.y; acc.z += v.z; acc.w += v.w;
        }
        j += 3;
    }
    int rem = end - j;
    if (act && g < rem) {
        int s = col[j + g];
        float4 v = Y4[s * 10 + q];
        acc.x += v.x; acc.y += v.y; acc.z += v.z; acc.w += v.w;
    }

    acc.x += __shfl_sync(0xffffffffu, acc.x, lane + 10) + __shfl_sync(0xffffffffu, acc.x, lane + 20);
    acc.y += __shfl_sync(0xffffffffu, acc.y, lane + 10) + __shfl_sync(0xffffffffu, acc.y, lane + 20);
    acc.z += __shfl_sync(0xffffffffu, acc.z, lane + 10) + __shfl_sync(0xffffffffu, acc.z, lane + 20);
    acc.w += __shfl_sync(0xffffffffu, acc.w, lane + 10) + __shfl_sync(0xffffffffu, acc.w, lane + 20);

    bool own = (lane < 10);
    if (own) {
        acc.x += b2[lane * 4 + 0];
        acc.y += b2[lane * 4 + 1];
        acc.z += b2[lane * 4 + 2];
        acc.w += b2[lane * 4 + 3];
    }
    float m = own ? fmaxf(fmaxf(acc.x, acc.y), fmaxf(acc.z, acc.w)) : -1e30f;
#pragma unroll
    for (int off = 16; off; off >>= 1)
        m = fmaxf(m, __shfl_xor_sync(0xffffffffu, m, off));
    float e0 = __expf(acc.x - m);
    float e1 = __expf(acc.y - m);
    float e2 = __expf(acc.z - m);
    float e3 = __expf(acc.w - m);
    float s = own ? (e0 + e1) + (e2 + e3) : 0.f;
#pragma unroll
    for (int off = 16; off; off >>= 1)
        s += __shfl_xor_sync(0xffffffffu, s, off);
    float inv = 1.f / s;
    if (own) {
        float* o = out + w * C + lane * 4;
        o[0] = e0 * inv;
        o[1] = e1 * inv;
        o[2] = e2 * inv;
        o[3] = e3 * inv;
    }
}

// ---------------- launch ----------------
extern "C" void kernel_launch(void* const* d_in, const int* in_sizes, int n_in,
                              void* d_out, int out_size) {
    const float* h   = (const float*)d_in[0];
    const int*   adj = (const int*)d_in[1];
    const float* W1  = (const float*)d_in[2];
    const float* b1  = (const float*)d_in[3];
    const float* W2  = (const float*)d_in[4];
    const float* b2  = (const float*)d_in[5];
    float* out = (float*)d_out;

    int n = in_sizes[0] / D;
    int e = in_sizes[1] / 2;
    if (n > MAXN) n = MAXN;
    if (e > MAXE) e = MAXE;

    cudaFuncSetAttribute(k_fused, cudaFuncAttributeMaxDynamicSharedMemorySize, SM_BYTES);

    k_init<<<(n + 255) / 256, 256>>>(n);
    k_build<<<(e + 255) / 256, 256>>>((const int2*)adj, e);

    k_fused<<<(n + 63) / 64, 256, SM_BYTES>>>(h, W1, b1, W2, n);
    k_agg2_softmax<<<(n * 32 + 255) / 256, 256>>>(b2, out, n);
}

// round 13
// speedup vs baseline: 1.5839x; 1.2414x over previous
#include <cuda_runtime.h>
#include <cuda_bf16.h>
#include <math.h>
#include <cstdint>

#define MAXN 100000
#define MAXE 1200000
#define D    64
#define HID  128
#define C    40
#define CAP  128

// ---------------- device scratch ----------------
__device__ int   d_deg[MAXN];
__device__ int   d_colb[(size_t)MAXN * CAP];
__device__ __align__(16) float d_agg1[(size_t)MAXN * D];   // 25.6 MB
__device__ __align__(16) float d_y[(size_t)MAXN * C];

// ---------------- tf32 helpers ----------------
__device__ __forceinline__ uint32_t f2tf32(float x) {
    uint32_t r;
    asm("cvt.rna.tf32.f32 %0, %1;" : "=r"(r) : "f"(x));
    return r;
}
#define MMA_TF32(cc, a0, a1, a2, a3, b0, b1) \
    asm volatile("mma.sync.aligned.m16n8k8.row.col.f32.tf32.tf32.f32 " \
        "{%0,%1,%2,%3}, {%4,%5,%6,%7}, {%8,%9}, {%0,%1,%2,%3};" \
        : "+f"((cc)[0]), "+f"((cc)[1]), "+f"((cc)[2]), "+f"((cc)[3]) \
        : "r"(a0), "r"(a1), "r"(a2), "r"(a3), "r"(b0), "r"(b1))

// ---------------- build ----------------
__global__ void k_init(int n) {
    int i = blockIdx.x * blockDim.x + threadIdx.x;
    if (i < n) d_deg[i] = 0;
}

__global__ void k_build(const int2* __restrict__ adj, int e) {
    int i = blockIdx.x * blockDim.x + threadIdx.x;
    if (i < e) {
        int2 ed = adj[i];
        int p = atomicAdd(&d_deg[ed.y], 1);
        d_colb[ed.y * CAP + p] = ed.x;
    }
}

// ---------------- standalone layer-1 gather (warp per node, full occupancy) ----------------
__global__ void k_agg1(const float* __restrict__ h, int n) {
    int w = (blockIdx.x * blockDim.x + threadIdx.x) >> 5;
    int lane = threadIdx.x & 31;
    if (w >= n) return;
    int half = lane >> 4;
    int q = lane & 15;
    const float4* h4 = (const float4*)h;

    float4 acc = make_float4(0.f, 0.f, 0.f, 0.f);
    if (half == 0) acc = h4[w * 16 + q];          // self-loop
    const int* col = d_colb + w * CAP;
    int end = d_deg[w];
    int j = 0;
    for (; j + 7 < end; j += 8) {                 // 8 edges, 4 loads/half in flight
        int s0 = col[j + half];
        int s1 = col[j + 2 + half];
        int s2 = col[j + 4 + half];
        int s3 = col[j + 6 + half];
        float4 v0 = h4[s0 * 16 + q];
        float4 v1 = h4[s1 * 16 + q];
        float4 v2 = h4[s2 * 16 + q];
        float4 v3 = h4[s3 * 16 + q];
        acc.x += (v0.x + v1.x) + (v2.x + v3.x);
        acc.y += (v0.y + v1.y) + (v2.y + v3.y);
        acc.z += (v0.z + v1.z) + (v2.z + v3.z);
        acc.w += (v0.w + v1.w) + (v2.w + v3.w);
    }
    if (j + 3 < end) {
        int s0 = col[j + half];
        int s1 = col[j + 2 + half];
        float4 v0 = h4[s0 * 16 + q];
        float4 v1 = h4[s1 * 16 + q];
        acc.x += v0.x + v1.x;
        acc.y += v0.y + v1.y;
        acc.z += v0.z + v1.z;
        acc.w += v0.w + v1.w;
        j += 4;
    }
    if (j + 1 < end) {
        int s = col[j + half];
        float4 v = h4[s * 16 + q];
        acc.x += v.x; acc.y += v.y; acc.z += v.z; acc.w += v.w;
        j += 2;
    }
    if (j < end && half == 0) {
        int s = col[j];
        float4 v = h4[s * 16 + q];
        acc.x += v.x; acc.y += v.y; acc.z += v.z; acc.w += v.w;
    }
    acc.x += __shfl_xor_sync(0xffffffffu, acc.x, 16);
    acc.y += __shfl_xor_sync(0xffffffffu, acc.y, 16);
    acc.z += __shfl_xor_sync(0xffffffffu, acc.z, 16);
    acc.w += __shfl_xor_sync(0xffffffffu, acc.w, 16);
    if (half == 0)
        ((float4*)d_agg1)[w * 16 + q] = acc;
}

// ---------------- TF32 mma: GEMM1 + ReLU + GEMM2 (64 nodes/block) ----------------
// smem layout (word offsets):
// phase 1: SA_HI 0 [64x68] | SA_LO 4352 [64x68] | W1_HI 8704 [64x136] | W1_LO 17408 [64x136]
// phase 2: X_HI 0 [64x132] | X_LO 8448 [64x132] | W2_HI 16896 [128x40] | W2_LO 22016 [128x40]
#define WO_SA_HI 0
#define WO_SA_LO 4352
#define WO_W1_HI 8704
#define WO_W1_LO 17408
#define WO_X_HI  0
#define WO_X_LO  8448
#define WO_W2_HI 16896
#define WO_W2_LO 22016
#define SM_WORDS 27136
#define SM_BYTES (SM_WORDS * 4)   // 108544

__global__ void __launch_bounds__(256, 2) k_gemm(const float* __restrict__ b1,
                                                 const float* __restrict__ W1,
                                                 const float* __restrict__ W2,
                                                 int n) {
    extern __shared__ uint32_t smw[];
    int tid = threadIdx.x;
    int w = tid >> 5, lane = tid & 31;
    int g = lane >> 2, tg = lane & 3;
    int node0 = blockIdx.x * 64;

    // ---- W1 split -> smem [k][136] hi/lo ----
    {
        uint32_t* WH = smw + WO_W1_HI;
        uint32_t* WL = smw + WO_W1_LO;
#pragma unroll
        for (int i = 0; i < 32; i++) {
            int idx = tid + i * 256;
            int k = idx >> 7, nn = idx & 127;
            float v = W1[idx];
            uint32_t hi = f2tf32(v);
            WH[k * 136 + nn] = hi;
            WL[k * 136 + nn] = f2tf32(v - __uint_as_float(hi));
        }
    }

    // ---- load A tile from d_agg1, split -> AH/AL [node][68] ----
    {
        uint32_t* AH = smw + WO_SA_HI;
        uint32_t* AL = smw + WO_SA_LO;
        int base = node0 * D;
        int lim = (n - node0) * D;     // elements in range (may exceed 4096)
#pragma unroll
        for (int i = 0; i < 16; i++) {
            int idx = tid + i * 256;   // node = idx>>6, k = idx&63
            float v = (idx < lim) ? d_agg1[base + idx] : 0.f;
            uint32_t hi = f2tf32(v);
            int a = (idx >> 6) * 68 + (idx & 63);
            AH[a] = hi;
            AL[a] = f2tf32(v - __uint_as_float(hi));
        }
    }
    __syncthreads();

    // ---- phase 1: x1 = relu(A @ W1 + b1) via tf32 mma (2-split, 3 products) ----
    float c1[8][4];
    {
        const uint32_t* AH = smw + WO_SA_HI;
        const uint32_t* AL = smw + WO_SA_LO;
        const uint32_t* WH = smw + WO_W1_HI;
        const uint32_t* WL = smw + WO_W1_LO;
        int mt = w & 3;
        int nhalf = w >> 2;
#pragma unroll
        for (int nt = 0; nt < 8; nt++)
#pragma unroll
            for (int i = 0; i < 4; i++) c1[nt][i] = 0.f;

#pragma unroll
        for (int kt = 0; kt < 8; kt++) {
            int ar = (mt * 16 + g) * 68 + kt * 8 + tg;
            uint32_t ah0 = AH[ar],     ah1 = AH[ar + 8 * 68];
            uint32_t ah2 = AH[ar + 4], ah3 = AH[ar + 8 * 68 + 4];
            uint32_t al0 = AL[ar],     al1 = AL[ar + 8 * 68];
            uint32_t al2 = AL[ar + 4], al3 = AL[ar + 8 * 68 + 4];
#pragma unroll
            for (int nt = 0; nt < 8; nt++) {
                int br = (kt * 8 + tg) * 136 + nhalf * 64 + nt * 8 + g;
                uint32_t bh0 = WH[br], bh1 = WH[br + 4 * 136];
                uint32_t bl0 = WL[br], bl1 = WL[br + 4 * 136];
                MMA_TF32(c1[nt], ah0, ah1, ah2, ah3, bh0, bh1);
                MMA_TF32(c1[nt], ah0, ah1, ah2, ah3, bl0, bl1);
                MMA_TF32(c1[nt], al0, al1, al2, al3, bh0, bh1);
            }
        }
    }
    __syncthreads();   // SA/W1 reads done -> overlay X

    // ---- write x1 (bias+relu) as tf32 splits into X_HI/X_LO [node][132] ----
    {
        uint32_t* XH = smw + WO_X_HI;
        uint32_t* XL = smw + WO_X_LO;
        int mt = w & 3;
        int nhalf = w >> 2;
#pragma unroll
        for (int nt = 0; nt < 8; nt++) {
            int col = nhalf * 64 + nt * 8 + tg * 2;
            float2 bb = *(const float2*)&b1[col];
#pragma unroll
            for (int ip = 0; ip < 2; ip++) {
                int row = mt * 16 + g + ip * 8;
                float v0 = fmaxf(c1[nt][ip * 2 + 0] + bb.x, 0.f);
                float v1 = fmaxf(c1[nt][ip * 2 + 1] + bb.y, 0.f);
                uint32_t h0 = f2tf32(v0), h1 = f2tf32(v1);
                uint32_t l0 = f2tf32(v0 - __uint_as_float(h0));
                uint32_t l1 = f2tf32(v1 - __uint_as_float(h1));
                *(uint2*)&XH[row * 132 + col] = make_uint2(h0, h1);
                *(uint2*)&XL[row * 132 + col] = make_uint2(l0, l1);
            }
        }
    }
    // ---- W2 split (L2-hot) ----
    {
        uint32_t* WH = smw + WO_W2_HI;
        uint32_t* WL = smw + WO_W2_LO;
#pragma unroll
        for (int i = 0; i < 20; i++) {
            int idx = tid + i * 256;
            float v = W2[idx];
            uint32_t hi = f2tf32(v);
            WH[idx] = hi;
            WL[idx] = f2tf32(v - __uint_as_float(hi));
        }
    }
    __syncthreads();

    // ---- phase 2: y = x1 @ W2 via tf32 mma; 2-way k-split ----
    float c2[5][4];
    {
        const uint32_t* XH = smw + WO_X_HI;
        const uint32_t* XL = smw + WO_X_LO;
        const uint32_t* WH = smw + WO_W2_HI;
        const uint32_t* WL = smw + WO_W2_LO;
        int mt = w & 3;
        int kh = w >> 2;
#pragma unroll
        for (int nt = 0; nt < 5; nt++)
#pragma unroll
            for (int i = 0; i < 4; i++) c2[nt][i] = 0.f;

#pragma unroll
        for (int kt = 0; kt < 8; kt++) {
            int k0 = kh * 64 + kt * 8;
            int ar = (mt * 16 + g) * 132 + k0 + tg;
            uint32_t ah0 = XH[ar],     ah1 = XH[ar + 8 * 132];
            uint32_t ah2 = XH[ar + 4], ah3 = XH[ar + 8 * 132 + 4];
            uint32_t al0 = XL[ar],     al1 = XL[ar + 8 * 132];
            uint32_t al2 = XL[ar + 4], al3 = XL[ar + 8 * 132 + 4];
#pragma unroll
            for (int nt = 0; nt < 5; nt++) {
                int br = (k0 + tg) * 40 + nt * 8 + g;
                uint32_t bh0 = WH[br], bh1 = WH[br + 4 * 40];
                uint32_t bl0 = WL[br], bl1 = WL[br + 4 * 40];
                MMA_TF32(c2[nt], ah0, ah1, ah2, ah3, bh0, bh1);
                MMA_TF32(c2[nt], ah0, ah1, ah2, ah3, bl0, bl1);
                MMA_TF32(c2[nt], al0, al1, al2, al3, bh0, bh1);
            }
        }
    }
    __syncthreads();

    // ---- reduce k-halves and write y ----
    {
        float* SC = (float*)(smw + WO_X_HI);   // [64][44] scratch
        int mt = w & 3;
        int kh = w >> 2;
        if (kh == 1) {
#pragma unroll
            for (int nt = 0; nt < 5; nt++)
#pragma unroll
                for (int ip = 0; ip < 2; ip++) {
                    int row = mt * 16 + g + ip * 8;
                    int col = nt * 8 + tg * 2;
                    *(float2*)&SC[row * 44 + col] =
                        make_float2(c2[nt][ip * 2], c2[nt][ip * 2 + 1]);
                }
        }
        __syncthreads();
        if (kh == 0) {
#pragma unroll
            for (int nt = 0; nt < 5; nt++)
#pragma unroll
                for (int ip = 0; ip < 2; ip++) {
                    int row = mt * 16 + g + ip * 8;
                    int gn = node0 + row;
                    int col = nt * 8 + tg * 2;
                    float2 o = *(float2*)&SC[row * 44 + col];
                    o.x += c2[nt][ip * 2];
                    o.y += c2[nt][ip * 2 + 1];
                    if (gn < n) *(float2*)&d_y[gn * C + col] = o;
                }
        }
    }
}

// ---------------- layer-2 aggregation + bias + softmax ----------------
__global__ void k_agg2_softmax(const float* __restrict__ b2, float* __restrict__ out, int n) {
    int w = (blockIdx.x * blockDim.x + threadIdx.x) >> 5;
    int lane = threadIdx.x & 31;
    if (w >= n) return;

    int g = lane / 10;
    int q = lane - g * 10;
    bool act = (lane < 30);
    const float4* Y4 = (const float4*)d_y;

    float4 acc = make_float4(0.f, 0.f, 0.f, 0.f);
    if (act && g == 0) acc = Y4[w * 10 + q];

    const int* col = d_colb + w * CAP;
    int end = d_deg[w];
    int j = 0;
    for (; j + 11 < end; j += 12) {
        if (act) {
            int s0 = col[j + g];
            int s1 = col[j + 3 + g];
            int s2 = col[j + 6 + g];
            int s3 = col[j + 9 + g];
            float4 v0 = Y4[s0 * 10 + q];
            float4 v1 = Y4[s1 * 10 + q];
            float4 v2 = Y4[s2 * 10 + q];
            float4 v3 = Y4[s3 * 10 + q];
            acc.x += (v0.x + v1.x) + (v2.x + v3.x);
            acc.y += (v0.y + v1.y) + (v2.y + v3.y);
            acc.z += (v0.z + v1.z) + (v2.z + v3.z);
            acc.w += (v0.w + v1.w) + (v2.w + v3.w);
        }
    }
    if (j + 5 < end) {
        if (act) {
            int s0 = col[j + g];
            int s1 = col[j + 3 + g];
            float4 v0 = Y4[s0 * 10 + q];
            float4 v1 = Y4[s1 * 10 + q];
            acc.x += v0.x + v1.x;
            acc.y += v0.y + v1.y;
            acc.z += v0.z + v1.z;
            acc.w += v0.w + v1.w;
        }
        j += 6;
    }
    if (j + 2 < end) {
        if (act) {
            int s = col[j + g];
            float4 v = Y4[s * 10 + q];
            acc.x += v.x; acc.y += v.y; acc.z += v.z; acc.w += v.w;
        }
        j += 3;
    }
    int rem = end - j;
    if (act && g < rem) {
        int s = col[j + g];
        float4 v = Y4[s * 10 + q];
        acc.x += v.x; acc.y += v.y; acc.z += v.z; acc.w += v.w;
    }

    acc.x += __shfl_sync(0xffffffffu, acc.x, lane + 10) + __shfl_sync(0xffffffffu, acc.x, lane + 20);
    acc.y += __shfl_sync(0xffffffffu, acc.y, lane + 10) + __shfl_sync(0xffffffffu, acc.y, lane + 20);
    acc.z += __shfl_sync(0xffffffffu, acc.z, lane + 10) + __shfl_sync(0xffffffffu, acc.z, lane + 20);
    acc.w += __shfl_sync(0xffffffffu, acc.w, lane + 10) + __shfl_sync(0xffffffffu, acc.w, lane + 20);

    bool own = (lane < 10);
    if (own) {
        acc.x += b2[lane * 4 + 0];
        acc.y += b2[lane * 4 + 1];
        acc.z += b2[lane * 4 + 2];
        acc.w += b2[lane * 4 + 3];
    }
    float m = own ? fmaxf(fmaxf(acc.x, acc.y), fmaxf(acc.z, acc.w)) : -1e30f;
#pragma unroll
    for (int off = 16; off; off >>= 1)
        m = fmaxf(m, __shfl_xor_sync(0xffffffffu, m, off));
    float e0 = __expf(acc.x - m);
    float e1 = __expf(acc.y - m);
    float e2 = __expf(acc.z - m);
    float e3 = __expf(acc.w - m);
    float s = own ? (e0 + e1) + (e2 + e3) : 0.f;
#pragma unroll
    for (int off = 16; off; off >>= 1)
        s += __shfl_xor_sync(0xffffffffu, s, off);
    float inv = 1.f / s;
    if (own) {
        float* o = out + w * C + lane * 4;
        o[0] = e0 * inv;
        o[1] = e1 * inv;
        o[2] = e2 * inv;
        o[3] = e3 * inv;
    }
}

// ---------------- launch ----------------
extern "C" void kernel_launch(void* const* d_in, const int* in_sizes, int n_in,
                              void* d_out, int out_size) {
    const float* h   = (const float*)d_in[0];
    const int*   adj = (const int*)d_in[1];
    const float* W1  = (const float*)d_in[2];
    const float* b1  = (const float*)d_in[3];
    const float* W2  = (const float*)d_in[4];
    const float* b2  = (const float*)d_in[5];
    float* out = (float*)d_out;

    int n = in_sizes[0] / D;
    int e = in_sizes[1] / 2;
    if (n > MAXN) n = MAXN;
    if (e > MAXE) e = MAXE;

    cudaFuncSetAttribute(k_gemm, cudaFuncAttributeMaxDynamicSharedMemorySize, SM_BYTES);

    k_init<<<(n + 255) / 256, 256>>>(n);
    k_build<<<(e + 255) / 256, 256>>>((const int2*)adj, e);

    k_agg1<<<(n * 32 + 255) / 256, 256>>>(h, n);
    k_gemm<<<(n + 63) / 64, 256, SM_BYTES>>>(b1, W1, W2, n);
    k_agg2_softmax<<<(n * 32 + 255) / 256, 256>>>(b2, out, n);
}